// round 8
// baseline (speedup 1.0000x reference)
#include <cuda_runtime.h>

// Problem constants (fixed: B_SZ=2, SEQ=4096, D=4096, R=8, U=4)
#define D_DIM  4096
#define D4     1024          // float4 per row
#define R_DIM  8
#define U_DIM  4
#define N_ROWS 8192

#define SPLITK 8
#define KQ4    (D4 / SPLITK) // 128 float4 per k-slice

// Split-k partials for t: 8 x 8192 x 8 floats = 2 MB (static, allowed).
__device__ float g_tp[SPLITK][N_ROWS * R_DIM];

// ======================= Phase 1: partial t over one k-slice ================
// Block = (rowTile, kq): 32 rows x 512 k-elems. Warp owns 4 rows, lanes split
// k. 2048 blocks total across two launches (launch split is for ncu phase-1
// visibility: 4-kernel cycle puts the profiled 6th launch on phase1b).
#define P1_THREADS 256
#define RPW 4                // rows per warp
#define P1_ROWS_PER_BLOCK (RPW * (P1_THREADS / 32))   // 32

__global__ __launch_bounds__(P1_THREADS)
void phase1_kernel(const float* __restrict__ x,
                   const float* __restrict__ B,
                   int kq0)
{
    const int tid  = threadIdx.x;
    const int w    = tid >> 5;
    const int lane = tid & 31;
    const int row0 = blockIdx.x * P1_ROWS_PER_BLOCK + w * RPW;
    const int kq   = kq0 + blockIdx.y;
    const int kb4  = kq * KQ4;

    const float4* __restrict__ x4 = reinterpret_cast<const float4*>(x);
    const float4* __restrict__ B4 = reinterpret_cast<const float4*>(B);

    float acc[RPW][R_DIM];
    #pragma unroll
    for (int a = 0; a < RPW; a++)
        #pragma unroll
        for (int r = 0; r < R_DIM; r++) acc[a][r] = 0.f;

    #pragma unroll 2
    for (int kt = 0; kt < KQ4 / 32; kt++) {       // 4 k-tiles of 32 float4
        const int i4 = kb4 + kt * 32 + lane;
        float4 xv[RPW];
        #pragma unroll
        for (int a = 0; a < RPW; a++)
            xv[a] = __ldcs(&x4[(size_t)(row0 + a) * D4 + i4]);  // stream
        #pragma unroll
        for (int r = 0; r < R_DIM; r++) {
            const float4 bv = B4[r * D4 + i4];                  // L1/L2-hot
            #pragma unroll
            for (int a = 0; a < RPW; a++)
                acc[a][r] += xv[a].x * bv.x + xv[a].y * bv.y
                           + xv[a].z * bv.z + xv[a].w * bv.w;
        }
    }

    // Butterfly-reduce the 32 accumulators across lanes.
    #pragma unroll
    for (int a = 0; a < RPW; a++)
        #pragma unroll
        for (int r = 0; r < R_DIM; r++)
            #pragma unroll
            for (int off = 16; off > 0; off >>= 1)
                acc[a][r] += __shfl_xor_sync(0xFFFFFFFFu, acc[a][r], off);

    // Lane l writes (a = l>>3, r = l&7): 128B coalesced per warp.
    const int a = lane >> 3;
    const int r = lane & 7;
    g_tp[kq][(size_t)(row0 + a) * R_DIM + r] = acc[a][r];
}

// ======================= Phase 2: out[n,d] = base[n,d] + sum_r t[n,r]*A[d,r] =
// Folds the 8 split-k partials + scale = P @ v into the t-tile. Thread pins
// its 4 columns' A rows (8 float4) and streams NT2 rows with MLP=8 batched
// base loads. base/out use .cs (evict-first) — zero reuse.
#define P2_THREADS 256
#define NT2 32                // rows per block
#define DT4 256               // float4 columns per block

__global__ __launch_bounds__(P2_THREADS)
void phase2_kernel(const float* __restrict__ base,
                   const float* __restrict__ A,
                   const float* __restrict__ P,
                   const float* __restrict__ v,
                   float* __restrict__ out,
                   int rowblk0)
{
    __shared__ float ts[NT2][R_DIM];          // 1 KB

    const int tid  = threadIdx.x;
    const int row0 = (rowblk0 + blockIdx.x) * NT2;
    const int d4   = blockIdx.y * DT4 + tid;  // this thread's float4 column

    const float4* __restrict__ A4    = reinterpret_cast<const float4*>(A);
    const float4* __restrict__ base4 = reinterpret_cast<const float4*>(base);
    float4* __restrict__ out4        = reinterpret_cast<float4*>(out);

    // Fold split-k partials + scale: thread owns one (m, r).
    {
        const int m = tid >> 3, r = tid & 7;
        const size_t idx = (size_t)(row0 + m) * R_DIM + r;
        float s = 0.f;
        #pragma unroll
        for (int q = 0; q < SPLITK; q++) s += g_tp[q][idx];
        float sc = 0.f;
        #pragma unroll
        for (int u = 0; u < U_DIM; u++) sc += P[r * U_DIM + u] * v[u];
        ts[m][r] = s * sc;
    }

    // A rows for this thread's 4 consecutive d's: 128 contiguous bytes.
    float4 a[8];
    #pragma unroll
    for (int j = 0; j < 8; j++)
        a[j] = A4[(size_t)d4 * 8 + j];

    __syncthreads();

    #pragma unroll 1
    for (int c = 0; c < NT2; c += 8) {
        float4 bv[8];                          // batch 8 loads (MLP=8)
        #pragma unroll
        for (int i = 0; i < 8; i++)
            bv[i] = __ldcs(&base4[(size_t)(row0 + c + i) * D4 + d4]);

        #pragma unroll
        for (int i = 0; i < 8; i++) {
            const int mm = c + i;
            const float t0 = ts[mm][0], t1 = ts[mm][1], t2 = ts[mm][2], t3 = ts[mm][3];
            const float t4 = ts[mm][4], t5 = ts[mm][5], t6 = ts[mm][6], t7 = ts[mm][7];
            float4 o;
            o.x = bv[i].x + t0*a[0].x + t1*a[0].y + t2*a[0].z + t3*a[0].w
                          + t4*a[1].x + t5*a[1].y + t6*a[1].z + t7*a[1].w;
            o.y = bv[i].y + t0*a[2].x + t1*a[2].y + t2*a[2].z + t3*a[2].w
                          + t4*a[3].x + t5*a[3].y + t6*a[3].z + t7*a[3].w;
            o.z = bv[i].z + t0*a[4].x + t1*a[4].y + t2*a[4].z + t3*a[4].w
                          + t4*a[5].x + t5*a[5].y + t6*a[5].z + t7*a[5].w;
            o.w = bv[i].w + t0*a[6].x + t1*a[6].y + t2*a[6].z + t3*a[6].w
                          + t4*a[7].x + t5*a[7].y + t6*a[7].z + t7*a[7].w;
            __stcs(&out4[(size_t)(row0 + mm) * D4 + d4], o);
        }
    }
}

extern "C" void kernel_launch(void* const* d_in, const int* in_sizes, int n_in,
                              void* d_out, int out_size)
{
    const float* x    = (const float*)d_in[0];
    const float* base = (const float*)d_in[1];
    const float* A    = (const float*)d_in[2];
    const float* B    = (const float*)d_in[3];
    const float* P    = (const float*)d_in[4];
    const float* v    = (const float*)d_in[5];
    float* out = (float*)d_out;

    // 4 launches per replay -> ncu's 6th-launch capture (index 5 mod 4 = 1)
    // lands on phase1b, finally exposing phase-1 metrics.
    dim3 g1(N_ROWS / P1_ROWS_PER_BLOCK, SPLITK / 2);   // (256, 4) each
    phase1_kernel<<<g1, P1_THREADS>>>(x, B, 0);        // phase1a: kq 0..3
    phase1_kernel<<<g1, P1_THREADS>>>(x, B, SPLITK / 2); // phase1b: kq 4..7

    dim3 g2(N_ROWS / NT2 / 2, D_DIM / (DT4 * 4));      // (128, 4) each
    phase2_kernel<<<g2, P2_THREADS>>>(base, A, P, v, out, 0);
    phase2_kernel<<<g2, P2_THREADS>>>(base, A, P, v, out, N_ROWS / NT2 / 2);
}

// round 9
// speedup vs baseline: 1.1597x; 1.1597x over previous
#include <cuda_runtime.h>

// Problem constants (fixed: B_SZ=2, SEQ=4096, D=4096, R=8, U=4)
#define D_DIM  4096
#define D4     1024          // float4 per row
#define R_DIM  8
#define U_DIM  4
#define N_ROWS 8192

#define SPLITK 4
#define KQ4    (D4 / SPLITK) // 256 float4 per k-slice

// Split-k partials for t: 4 x 8192 x 8 floats = 1 MB (static, allowed).
__device__ float g_tp[SPLITK][N_ROWS * R_DIM];

// Packed f32x2 FMA: d = a*b + d (two fp32 lanes per instruction, Blackwell FFMA2)
__device__ __forceinline__ void fma_f32x2(unsigned long long& d,
                                          unsigned long long a,
                                          unsigned long long b)
{
    asm("fma.rn.f32x2 %0, %1, %2, %0;" : "+l"(d) : "l"(a), "l"(b));
}

// ======================= Phase 1: partial t over one k-slice ================
// Block = (rowTile, kq): 32 rows x 1024 k-elems. Warp owns 4 rows, lanes
// split k. x/B loaded as ulonglong2 -> each .x/.y is an f32x2 pair, fed
// straight into packed FFMA2 (64 per tile instead of 128 FFMA): halves the
// FMA-pipe issue load that was serializing with the DRAM stream.
#define P1_THREADS 256
#define RPW 4                // rows per warp
#define P1_ROWS_PER_BLOCK (RPW * (P1_THREADS / 32))   // 32

__global__ __launch_bounds__(P1_THREADS)
void phase1_kernel(const float* __restrict__ x,
                   const float* __restrict__ B)
{
    const int tid  = threadIdx.x;
    const int w    = tid >> 5;
    const int lane = tid & 31;
    const int row0 = blockIdx.x * P1_ROWS_PER_BLOCK + w * RPW;
    const int kq   = blockIdx.y;
    const int kb4  = kq * KQ4;

    const ulonglong2* __restrict__ x2 = reinterpret_cast<const ulonglong2*>(x);
    const ulonglong2* __restrict__ B2 = reinterpret_cast<const ulonglong2*>(B);

    unsigned long long acc2[RPW][R_DIM];     // f32x2 accumulators
    #pragma unroll
    for (int a = 0; a < RPW; a++)
        #pragma unroll
        for (int r = 0; r < R_DIM; r++) acc2[a][r] = 0ull;   // (+0.f, +0.f)

    #pragma unroll 2
    for (int kt = 0; kt < KQ4 / 32; kt++) {       // 8 k-tiles of 32 float4
        const int i4 = kb4 + kt * 32 + lane;      // float4 index == ulonglong2 index
        ulonglong2 xv[RPW];
        #pragma unroll
        for (int a = 0; a < RPW; a++)
            xv[a] = __ldcs(&x2[(size_t)(row0 + a) * D4 + i4]);  // stream
        #pragma unroll
        for (int r = 0; r < R_DIM; r++) {
            const ulonglong2 bv = B2[r * D4 + i4];              // L1/L2-hot
            #pragma unroll
            for (int a = 0; a < RPW; a++) {
                fma_f32x2(acc2[a][r], xv[a].x, bv.x);
                fma_f32x2(acc2[a][r], xv[a].y, bv.y);
            }
        }
    }

    // Unpack f32x2 accumulators (lo+hi), then butterfly-reduce across lanes.
    float acc[RPW][R_DIM];
    #pragma unroll
    for (int a = 0; a < RPW; a++)
        #pragma unroll
        for (int r = 0; r < R_DIM; r++) {
            float lo, hi;
            asm("mov.b64 {%0, %1}, %2;" : "=f"(lo), "=f"(hi) : "l"(acc2[a][r]));
            acc[a][r] = lo + hi;
        }

    #pragma unroll
    for (int a = 0; a < RPW; a++)
        #pragma unroll
        for (int r = 0; r < R_DIM; r++)
            #pragma unroll
            for (int off = 16; off > 0; off >>= 1)
                acc[a][r] += __shfl_xor_sync(0xFFFFFFFFu, acc[a][r], off);

    // Lane l writes (a = l>>3, r = l&7): 128B coalesced per warp.
    const int a = lane >> 3;
    const int r = lane & 7;
    g_tp[kq][(size_t)(row0 + a) * R_DIM + r] = acc[a][r];
}

// ======================= Phase 2: out[n,d] = base[n,d] + sum_r t[n,r]*A[d,r] =
// Exactly the proven R7 structure: fold 4 split-k partials + scale into the
// t-tile; thread pins its 4 columns' A rows (8 float4) and streams NT2 rows
// with MLP=4 batched base loads; .cs on the zero-reuse streams.
#define P2_THREADS 256
#define NT2 32                // rows per block
#define DT4 256               // float4 columns per block

__global__ __launch_bounds__(P2_THREADS)
void phase2_kernel(const float* __restrict__ base,
                   const float* __restrict__ A,
                   const float* __restrict__ P,
                   const float* __restrict__ v,
                   float* __restrict__ out)
{
    __shared__ float ts[NT2][R_DIM];          // 1 KB

    const int tid  = threadIdx.x;
    const int row0 = blockIdx.x * NT2;
    const int d4   = blockIdx.y * DT4 + tid;  // this thread's float4 column

    const float4* __restrict__ A4    = reinterpret_cast<const float4*>(A);
    const float4* __restrict__ base4 = reinterpret_cast<const float4*>(base);
    float4* __restrict__ out4        = reinterpret_cast<float4*>(out);

    // Fold split-k partials + scale: thread owns one (m, r).
    {
        const int m = tid >> 3, r = tid & 7;
        const size_t idx = (size_t)(row0 + m) * R_DIM + r;
        float s = 0.f;
        #pragma unroll
        for (int q = 0; q < SPLITK; q++) s += g_tp[q][idx];
        float sc = 0.f;
        #pragma unroll
        for (int u = 0; u < U_DIM; u++) sc += P[r * U_DIM + u] * v[u];
        ts[m][r] = s * sc;
    }

    // A rows for this thread's 4 consecutive d's: 128 contiguous bytes.
    float4 a[8];
    #pragma unroll
    for (int j = 0; j < 8; j++)
        a[j] = A4[(size_t)d4 * 8 + j];

    __syncthreads();

    #pragma unroll 2
    for (int c = 0; c < NT2; c += 4) {
        float4 bv[4];                          // batch 4 loads (MLP=4)
        #pragma unroll
        for (int i = 0; i < 4; i++)
            bv[i] = __ldcs(&base4[(size_t)(row0 + c + i) * D4 + d4]);

        #pragma unroll
        for (int i = 0; i < 4; i++) {
            const int mm = c + i;
            const float t0 = ts[mm][0], t1 = ts[mm][1], t2 = ts[mm][2], t3 = ts[mm][3];
            const float t4 = ts[mm][4], t5 = ts[mm][5], t6 = ts[mm][6], t7 = ts[mm][7];
            float4 o;
            o.x = bv[i].x + t0*a[0].x + t1*a[0].y + t2*a[0].z + t3*a[0].w
                          + t4*a[1].x + t5*a[1].y + t6*a[1].z + t7*a[1].w;
            o.y = bv[i].y + t0*a[2].x + t1*a[2].y + t2*a[2].z + t3*a[2].w
                          + t4*a[3].x + t5*a[3].y + t6*a[3].z + t7*a[3].w;
            o.z = bv[i].z + t0*a[4].x + t1*a[4].y + t2*a[4].z + t3*a[4].w
                          + t4*a[5].x + t5*a[5].y + t6*a[5].z + t7*a[5].w;
            o.w = bv[i].w + t0*a[6].x + t1*a[6].y + t2*a[6].z + t3*a[6].w
                          + t4*a[7].x + t5*a[7].y + t6*a[7].z + t7*a[7].w;
            __stcs(&out4[(size_t)(row0 + mm) * D4 + d4], o);
        }
    }
}

extern "C" void kernel_launch(void* const* d_in, const int* in_sizes, int n_in,
                              void* d_out, int out_size)
{
    const float* x    = (const float*)d_in[0];
    const float* base = (const float*)d_in[1];
    const float* A    = (const float*)d_in[2];
    const float* B    = (const float*)d_in[3];
    const float* P    = (const float*)d_in[4];
    const float* v    = (const float*)d_in[5];
    float* out = (float*)d_out;

    dim3 g1(N_ROWS / P1_ROWS_PER_BLOCK, SPLITK);  // (256, 4) = 1024 blocks
    phase1_kernel<<<g1, P1_THREADS>>>(x, B);

    dim3 g2(N_ROWS / NT2, D_DIM / (DT4 * 4));     // (256, 4) = 1024 blocks
    phase2_kernel<<<g2, P2_THREADS>>>(base, A, P, v, out);
}